// round 6
// baseline (speedup 1.0000x reference)
#include <cuda_runtime.h>
#include <math.h>
#include <stdint.h>

#define T_TOK 2048
#define DIM   1024
#define NEXP  8
#define FF    512
#define FSH   1024

// ---------------- scratch (__device__ globals: allocation-free) ----------------
__device__ int   g_count[NEXP];
__device__ int   g_tok[NEXP][T_TOK];
__device__ int   g_eslot[2][T_TOK];         // e*T_TOK + pos for each token's 2 experts
__device__ float g_ew[2][T_TOK];            // routing weights
__device__ float g_G [NEXP * T_TOK * FF];   // routed gate pre-act (compact rows)
__device__ float g_U [NEXP * T_TOK * FF];   // routed up (compact rows)
__device__ float g_O [NEXP * T_TOK * DIM];  // routed expert outputs (compact rows)
__device__ float g_Gs[T_TOK * FSH];         // shared gate pre-act
__device__ float g_Us[T_TOK * FSH];         // shared up

__device__ __forceinline__ float silu_f(float v) {
    return v / (1.f + __expf(-v));
}

__device__ __forceinline__ uint32_t f2tf32(float f) {
    uint32_t u;
    asm("cvt.rna.tf32.f32 %0, %1;" : "=r"(u) : "f"(f));
    return u;
}

__device__ __forceinline__ void mma_tf32(float4& c, const uint32_t a[4], const uint32_t b[2]) {
    asm volatile(
        "mma.sync.aligned.m16n8k8.row.col.f32.tf32.tf32.f32 "
        "{%0,%1,%2,%3}, {%4,%5,%6,%7}, {%8,%9}, {%0,%1,%2,%3};"
        : "+f"(c.x), "+f"(c.y), "+f"(c.z), "+f"(c.w)
        : "r"(a[0]), "r"(a[1]), "r"(a[2]), "r"(a[3]), "r"(b[0]), "r"(b[1]));
}

// ---------------- init ----------------
__global__ void k_init() {
    if (threadIdx.x < NEXP) g_count[threadIdx.x] = 0;
}

// ---------------- router (fp32 exact) ----------------
__global__ void k_router(const float* __restrict__ x, const float* __restrict__ Wr,
                         const float* __restrict__ bias) {
    int t    = blockIdx.x * blockDim.y + threadIdx.y;
    int lane = threadIdx.x;
    const float* xr = x + (size_t)t * DIM;
    float acc[NEXP];
#pragma unroll
    for (int e = 0; e < NEXP; e++) acc[e] = 0.f;
    for (int d = lane; d < DIM; d += 32) {
        float xv = xr[d];
        const float* w = Wr + d * NEXP;
#pragma unroll
        for (int e = 0; e < NEXP; e++) acc[e] += xv * w[e];
    }
#pragma unroll
    for (int o = 16; o > 0; o >>= 1)
#pragma unroll
        for (int e = 0; e < NEXP; e++)
            acc[e] += __shfl_down_sync(0xffffffffu, acc[e], o);
    if (lane == 0) {
        float v[NEXP];
#pragma unroll
        for (int e = 0; e < NEXP; e++) v[e] = acc[e] + bias[e];
        int i0 = 0;
#pragma unroll
        for (int e = 1; e < NEXP; e++) if (v[e] > v[i0]) i0 = e;
        int i1 = (i0 == 0) ? 1 : 0;
#pragma unroll
        for (int e = 0; e < NEXP; e++) if (e != i0 && v[e] > v[i1]) i1 = e;
        float e1    = __expf(v[i1] - v[i0]);
        float denom = 1.f + e1;
        float p0 = 1.f / denom, p1 = e1 / denom;
        int p = atomicAdd(&g_count[i0], 1);
        g_tok[i0][p] = t; g_eslot[0][t] = i0 * T_TOK + p; g_ew[0][t] = p0;
        p = atomicAdd(&g_count[i1], 1);
        g_tok[i1][p] = t; g_eslot[1][t] = i1 * T_TOK + p; g_ew[1][t] = p1;
    }
}

// =====================================================================
// tf32 tensor-core GEMM core (single-stage, round-2 proven structure).
// 128x128 block tile, BK=16, 8 warps (64x32 warp tile each).
// A [M,K] row-major; SWA=0: A = Ag (optionally row-gathered)
//                    SWA=1: A = silu(Ag) * Au   (compact rows, no gather)
// B [K,N] row-major.  C[m,n] = acc (plain store).
// =====================================================================
#define SPAD 136   // smem row stride in floats (pad -> conflict-free frag reads)

template<int SWA>
__device__ __forceinline__ void gemm_core(
    const float* __restrict__ Ag, const float* __restrict__ Au,
    const int* __restrict__ rowsA, int lda,
    const float* __restrict__ B, int ldb,
    float* __restrict__ C, int ldc,
    int Mcnt, int K)
{
    const int m0 = blockIdx.y * 128;
    if (m0 >= Mcnt) return;
    const int n0 = blockIdx.x * 128;

    __shared__ __align__(16) float As[16 * SPAD];
    __shared__ __align__(16) float Bs[16 * SPAD];

    const int tid  = threadIdx.x;
    const int lane = tid & 31;
    const int w    = tid >> 5;
    const int wm   = w >> 2;      // 0..1
    const int wn   = w & 3;       // 0..3

    // ---- A loader: thread covers row am, 8-wide k chunk aj ----
    const int am  = tid >> 1;
    const int aj  = tid & 1;
    const int amg = m0 + am;
    const bool aval = (amg < Mcnt);
    const float* Arg = Ag;
    const float* Aru = Au;
    if (aval) {
        int r = rowsA ? rowsA[amg] : amg;
        Arg = Ag + (size_t)r * lda + aj * 8;
        if (SWA) Aru = Au + (size_t)r * lda + aj * 8;
    }
    // ---- B loader: thread covers k-row bk, 8 consecutive n ----
    const int bk  = tid >> 4;
    const int bnt = tid & 15;
    const float* Bptr = B + (size_t)bk * ldb + n0 + bnt * 8;
    float* BsRow = &Bs[bk * SPAD + bnt * 8];
    float* AsCol = &As[aj * 8 * SPAD + am];

    float4 acc[4][4];
#pragma unroll
    for (int i = 0; i < 4; i++)
#pragma unroll
        for (int j = 0; j < 4; j++) acc[i][j] = make_float4(0.f, 0.f, 0.f, 0.f);

    const int fk = lane & 3;
    const int fr = lane >> 2;

    for (int k0 = 0; k0 < K; k0 += 16) {
        // stage A
        {
            float va[8] = {0,0,0,0,0,0,0,0};
            if (aval) {
                float4 t0 = *(const float4*)(Arg + k0);
                float4 t1 = *(const float4*)(Arg + k0 + 4);
                va[0]=t0.x; va[1]=t0.y; va[2]=t0.z; va[3]=t0.w;
                va[4]=t1.x; va[5]=t1.y; va[6]=t1.z; va[7]=t1.w;
                if (SWA) {
                    float4 u0 = *(const float4*)(Aru + k0);
                    float4 u1 = *(const float4*)(Aru + k0 + 4);
                    va[0] = silu_f(va[0]) * u0.x; va[1] = silu_f(va[1]) * u0.y;
                    va[2] = silu_f(va[2]) * u0.z; va[3] = silu_f(va[3]) * u0.w;
                    va[4] = silu_f(va[4]) * u1.x; va[5] = silu_f(va[5]) * u1.y;
                    va[6] = silu_f(va[6]) * u1.z; va[7] = silu_f(va[7]) * u1.w;
                }
            }
#pragma unroll
            for (int c = 0; c < 8; c++)
                AsCol[c * SPAD] = __uint_as_float(f2tf32(va[c]));
        }
        // stage B
        {
            float4 t0 = *(const float4*)(Bptr + (size_t)k0 * ldb);
            float4 t1 = *(const float4*)(Bptr + (size_t)k0 * ldb + 4);
            float vb[8] = {t0.x,t0.y,t0.z,t0.w,t1.x,t1.y,t1.z,t1.w};
#pragma unroll
            for (int c = 0; c < 8; c++)
                BsRow[c] = __uint_as_float(f2tf32(vb[c]));
        }
        __syncthreads();

#pragma unroll
        for (int ks = 0; ks < 2; ks++) {
            const int kb = ks * 8 + fk;
            uint32_t a[4][4], b[4][2];
#pragma unroll
            for (int i = 0; i < 4; i++) {
                const int m = wm * 64 + i * 16 + fr;
                a[i][0] = __float_as_uint(As[kb * SPAD + m]);
                a[i][1] = __float_as_uint(As[kb * SPAD + m + 8]);
                a[i][2] = __float_as_uint(As[(kb + 4) * SPAD + m]);
                a[i][3] = __float_as_uint(As[(kb + 4) * SPAD + m + 8]);
            }
#pragma unroll
            for (int j = 0; j < 4; j++) {
                const int n = wn * 32 + j * 8 + fr;
                b[j][0] = __float_as_uint(Bs[kb * SPAD + n]);
                b[j][1] = __float_as_uint(Bs[(kb + 4) * SPAD + n]);
            }
#pragma unroll
            for (int i = 0; i < 4; i++)
#pragma unroll
                for (int j = 0; j < 4; j++)
                    mma_tf32(acc[i][j], a[i], b[j]);
        }
        __syncthreads();
    }

    // ---- epilogue: plain stores ----
    const int er = lane >> 2;
    const int ec = (lane & 3) * 2;
#pragma unroll
    for (int i = 0; i < 4; i++) {
        const int mg0 = m0 + wm * 64 + i * 16 + er;
        const int mg1 = mg0 + 8;
#pragma unroll
        for (int j = 0; j < 4; j++) {
            const int n = n0 + wn * 32 + j * 8 + ec;
            if (mg0 < Mcnt)
                *(float2*)&C[(size_t)mg0 * ldc + n] = make_float2(acc[i][j].x, acc[i][j].y);
            if (mg1 < Mcnt)
                *(float2*)&C[(size_t)mg1 * ldc + n] = make_float2(acc[i][j].z, acc[i][j].w);
        }
    }
}

// ---------------- GEMM wrappers ----------------
// shared gate+up: z = mat (0 gate, 1 up)  -> grid 256 blocks
__global__ __launch_bounds__(256, 2)
void k_sh_gateup(const float* __restrict__ x, const float* __restrict__ Sg,
                 const float* __restrict__ Su) {
    const int mat = blockIdx.z;
    gemm_core<0>(x, nullptr, nullptr, DIM,
                 mat ? Su : Sg, FSH,
                 mat ? g_Us : g_Gs, FSH, T_TOK, DIM);
}

// shared down: A = silu(Gs)*Us on the fly, writes full out
__global__ __launch_bounds__(256, 2)
void k_sh_down(const float* __restrict__ Sd, float* __restrict__ out) {
    gemm_core<1>(g_Gs, g_Us, nullptr, FSH, Sd, DIM, out, DIM, T_TOK, FSH);
}

// routed gate+up: z = e*2 + mat  -> grid up to 512 blocks
__global__ __launch_bounds__(256, 2)
void k_moe_gateup(const float* __restrict__ x, const float* __restrict__ Wg,
                  const float* __restrict__ Wu) {
    const int z = blockIdx.z, e = z >> 1, mat = z & 1;
    const float* B = (mat ? Wu : Wg) + (size_t)e * DIM * FF;
    float*       C = (mat ? g_U : g_G) + (size_t)e * T_TOK * FF;
    gemm_core<0>(x, nullptr, g_tok[e], DIM, B, FF, C, FF, g_count[e], DIM);
}

// routed down: A = silu(G)*U on the fly, compact plain store to g_O
__global__ __launch_bounds__(256, 2)
void k_moe_down(const float* __restrict__ Wd) {
    const int e = blockIdx.z;
    gemm_core<1>(g_G + (size_t)e * T_TOK * FF, g_U + (size_t)e * T_TOK * FF,
                 nullptr, FF,
                 Wd + (size_t)e * FF * DIM, DIM,
                 g_O + (size_t)e * T_TOK * DIM, DIM, g_count[e], FF);
}

// ---------------- final combine: out[t] += w0*O[s0] + w1*O[s1] ----------------
__global__ void k_combine(float* __restrict__ out) {
    const int t = blockIdx.x;
    const int i = threadIdx.x * 4;
    const int   s0 = g_eslot[0][t], s1 = g_eslot[1][t];
    const float w0 = g_ew[0][t],    w1 = g_ew[1][t];
    float4 o = *(float4*)&out[(size_t)t * DIM + i];
    float4 a = *(const float4*)&g_O[(size_t)s0 * DIM + i];
    float4 b = *(const float4*)&g_O[(size_t)s1 * DIM + i];
    o.x += w0 * a.x + w1 * b.x;
    o.y += w0 * a.y + w1 * b.y;
    o.z += w0 * a.z + w1 * b.z;
    o.w += w0 * a.w + w1 * b.w;
    *(float4*)&out[(size_t)t * DIM + i] = o;
}

// ---------------- launch ----------------
extern "C" void kernel_launch(void* const* d_in, const int* in_sizes, int n_in,
                              void* d_out, int out_size) {
    const float* x    = (const float*)d_in[0];
    const float* Wr   = (const float*)d_in[1];
    const float* Wg   = (const float*)d_in[2];
    const float* Wu   = (const float*)d_in[3];
    const float* Wd   = (const float*)d_in[4];
    const float* Sg   = (const float*)d_in[5];
    const float* Su   = (const float*)d_in[6];
    const float* Sd   = (const float*)d_in[7];
    const float* bias = (const float*)d_in[8];
    float* out = (float*)d_out;

    k_init<<<1, 32>>>();
    k_router<<<T_TOK / 8, dim3(32, 8)>>>(x, Wr, bias);

    // gate+up projections (independent, big grids)
    k_sh_gateup<<<dim3(FSH / 128, T_TOK / 128, 2), 256>>>(x, Sg, Su);
    k_moe_gateup<<<dim3(FF / 128, T_TOK / 128, NEXP * 2), 256>>>(x, Wg, Wu);

    // down projections (silu fused into A loader)
    k_sh_down <<<dim3(DIM / 128, T_TOK / 128), 256>>>(Sd, out);
    k_moe_down<<<dim3(DIM / 128, T_TOK / 128, NEXP), 256>>>(Wd);

    // combine routed outputs into shared-expert output
    k_combine<<<T_TOK, 256>>>(out);
}

// round 10
// speedup vs baseline: 2.1637x; 2.1637x over previous
#include <cuda_runtime.h>
#include <math.h>
#include <stdint.h>

#define T_TOK 2048
#define DIM   1024
#define NEXP  8
#define FF    512
#define FSH   1024

// ---------------- scratch (__device__ globals: allocation-free) ----------------
__device__ int   g_count[NEXP];
__device__ int   g_tok[NEXP][T_TOK];
__device__ int   g_eslot[2][T_TOK];
__device__ float g_ew[2][T_TOK];
__device__ float g_G [NEXP * T_TOK * FF];   // routed gate pre-act (compact rows)
__device__ float g_U [NEXP * T_TOK * FF];   // routed up
__device__ float g_H [NEXP * T_TOK * FF];   // routed hidden silu(g)*u
__device__ float g_O [NEXP * T_TOK * DIM];  // routed expert outputs (compact rows)
__device__ float g_Gs[T_TOK * FSH];
__device__ float g_Us[T_TOK * FSH];
__device__ float g_Hs[T_TOK * FSH];

__device__ __forceinline__ float silu_f(float v) {
    return v / (1.f + __expf(-v));
}

__device__ __forceinline__ uint32_t f2tf32(float f) {
    uint32_t u;
    asm("cvt.rna.tf32.f32 %0, %1;" : "=r"(u) : "f"(f));
    return u;
}

__device__ __forceinline__ void mma_tf32(float4& c, const uint32_t a[4], const uint32_t b[2]) {
    asm volatile(
        "mma.sync.aligned.m16n8k8.row.col.f32.tf32.tf32.f32 "
        "{%0,%1,%2,%3}, {%4,%5,%6,%7}, {%8,%9}, {%0,%1,%2,%3};"
        : "+f"(c.x), "+f"(c.y), "+f"(c.z), "+f"(c.w)
        : "r"(a[0]), "r"(a[1]), "r"(a[2]), "r"(a[3]), "r"(b[0]), "r"(b[1]));
}

__device__ __forceinline__ void cp16(uint32_t saddr, const void* gptr) {
    asm volatile("cp.async.cg.shared.global [%0], [%1], 16;" :: "r"(saddr), "l"(gptr));
}
__device__ __forceinline__ void cp_commit() {
    asm volatile("cp.async.commit_group;");
}
template<int N> __device__ __forceinline__ void cp_wait() {
    asm volatile("cp.async.wait_group %0;" :: "n"(N));
}

// ---------------- init ----------------
__global__ void k_init() {
    if (threadIdx.x < NEXP) g_count[threadIdx.x] = 0;
}

// ---------------- router (fp32 exact) ----------------
__global__ void k_router(const float* __restrict__ x, const float* __restrict__ Wr,
                         const float* __restrict__ bias) {
    int t    = blockIdx.x * blockDim.y + threadIdx.y;
    int lane = threadIdx.x;
    const float* xr = x + (size_t)t * DIM;
    float acc[NEXP];
#pragma unroll
    for (int e = 0; e < NEXP; e++) acc[e] = 0.f;
    for (int d = lane; d < DIM; d += 32) {
        float xv = xr[d];
        const float* w = Wr + d * NEXP;
#pragma unroll
        for (int e = 0; e < NEXP; e++) acc[e] += xv * w[e];
    }
#pragma unroll
    for (int o = 16; o > 0; o >>= 1)
#pragma unroll
        for (int e = 0; e < NEXP; e++)
            acc[e] += __shfl_down_sync(0xffffffffu, acc[e], o);
    if (lane == 0) {
        float v[NEXP];
#pragma unroll
        for (int e = 0; e < NEXP; e++) v[e] = acc[e] + bias[e];
        int i0 = 0;
#pragma unroll
        for (int e = 1; e < NEXP; e++) if (v[e] > v[i0]) i0 = e;
        int i1 = (i0 == 0) ? 1 : 0;
#pragma unroll
        for (int e = 0; e < NEXP; e++) if (e != i0 && v[e] > v[i1]) i1 = e;
        float e1    = __expf(v[i1] - v[i0]);
        float denom = 1.f + e1;
        float p0 = 1.f / denom, p1 = e1 / denom;
        int p = atomicAdd(&g_count[i0], 1);
        g_tok[i0][p] = t; g_eslot[0][t] = i0 * T_TOK + p; g_ew[0][t] = p0;
        p = atomicAdd(&g_count[i1], 1);
        g_tok[i1][p] = t; g_eslot[1][t] = i1 * T_TOK + p; g_ew[1][t] = p1;
    }
}

// =====================================================================
// tf32 GEMM, cp.async 2-stage pipeline.
// 128x128 block tile, BK=16, 8 warps (64x32 warp tile).
// A [M,K] row-major (optional row gather).  B [K,N] row-major.
// SMEM: As row-major stride 20 (fragment reads conflict-free),
//       Bs row-major stride 136.
// tf32 rounding (cvt.rna) applied at fragment-load time.
// =====================================================================
#define ASTR 20
#define BSTR 136

__device__ __forceinline__ void gemm_core(
    const float* __restrict__ A, const int* __restrict__ rowsA, int lda,
    const float* __restrict__ B, int ldb,
    float* __restrict__ C, int ldc,
    int Mcnt, int K)
{
    const int m0 = blockIdx.y * 128;
    if (m0 >= Mcnt) return;
    const int n0 = blockIdx.x * 128;

    __shared__ __align__(16) float As[2][128 * ASTR];
    __shared__ __align__(16) float Bs[2][16 * BSTR];

    const int tid  = threadIdx.x;
    const int lane = tid & 31;
    const int w    = tid >> 5;
    const int wm   = w >> 2;
    const int wn   = w & 3;

    // A loader: row am, 8-float seg
    const int am  = tid >> 1;
    const int seg = tid & 1;
    const int amg = m0 + am;
    const bool aval = (amg < Mcnt);
    const float* Arow = A;
    if (aval) {
        int r = rowsA ? rowsA[amg] : amg;
        Arow = A + (size_t)r * lda + seg * 8;
    }
    // B loader: k-row bk, 8 consecutive n
    const int bk  = tid >> 4;
    const int bnt = tid & 15;
    const float* Bptr = B + (size_t)bk * ldb + n0 + bnt * 8;

    uint32_t sA[2], sB[2];
    sA[0] = (uint32_t)__cvta_generic_to_shared(&As[0][am * ASTR + seg * 8]);
    sA[1] = (uint32_t)__cvta_generic_to_shared(&As[1][am * ASTR + seg * 8]);
    sB[0] = (uint32_t)__cvta_generic_to_shared(&Bs[0][bk * BSTR + bnt * 8]);
    sB[1] = (uint32_t)__cvta_generic_to_shared(&Bs[1][bk * BSTR + bnt * 8]);

    // zero-fill rows that never get cp.async (stay zero all iterations)
    if (!aval) {
#pragma unroll
        for (int s = 0; s < 2; s++)
#pragma unroll
            for (int c = 0; c < 8; c++)
                As[s][am * ASTR + seg * 8 + c] = 0.f;
    }

    float4 acc[4][4];
#pragma unroll
    for (int i = 0; i < 4; i++)
#pragma unroll
        for (int j = 0; j < 4; j++) acc[i][j] = make_float4(0.f, 0.f, 0.f, 0.f);

    const int fk = lane & 3;
    const int fr = lane >> 2;
    const int nslab = K >> 4;

    // prologue: issue slab 0 into stage 0
    if (aval) { cp16(sA[0], Arow); cp16(sA[0] + 16, Arow + 4); }
    cp16(sB[0], Bptr); cp16(sB[0] + 16, Bptr + 4);
    cp_commit();

    for (int it = 0; it < nslab; it++) {
        const int cur = it & 1;
        if (it + 1 < nslab) {
            const int nxt = cur ^ 1;
            const int k1  = (it + 1) * 16;
            if (aval) { cp16(sA[nxt], Arow + k1); cp16(sA[nxt] + 16, Arow + k1 + 4); }
            const float* bsrc = Bptr + (size_t)k1 * ldb;
            cp16(sB[nxt], bsrc); cp16(sB[nxt] + 16, bsrc + 4);
            cp_commit();
            cp_wait<1>();
        } else {
            cp_wait<0>();
        }
        __syncthreads();

        const float* Ac = As[cur];
        const float* Bc = Bs[cur];
#pragma unroll
        for (int ks = 0; ks < 2; ks++) {
            const int kb = ks * 8 + fk;
            uint32_t a[4][4], b[4][2];
#pragma unroll
            for (int i = 0; i < 4; i++) {
                const int m = wm * 64 + i * 16 + fr;
                a[i][0] = f2tf32(Ac[m * ASTR + kb]);
                a[i][1] = f2tf32(Ac[(m + 8) * ASTR + kb]);
                a[i][2] = f2tf32(Ac[m * ASTR + kb + 4]);
                a[i][3] = f2tf32(Ac[(m + 8) * ASTR + kb + 4]);
            }
#pragma unroll
            for (int j = 0; j < 4; j++) {
                const int n = wn * 32 + j * 8 + fr;
                b[j][0] = f2tf32(Bc[kb * BSTR + n]);
                b[j][1] = f2tf32(Bc[(kb + 4) * BSTR + n]);
            }
#pragma unroll
            for (int i = 0; i < 4; i++)
#pragma unroll
                for (int j = 0; j < 4; j++)
                    mma_tf32(acc[i][j], a[i], b[j]);
        }
        __syncthreads();   // all warps done with 'cur' before it is refilled
    }

    // ---- epilogue: plain stores ----
    const int er = lane >> 2;
    const int ec = (lane & 3) * 2;
#pragma unroll
    for (int i = 0; i < 4; i++) {
        const int mg0 = m0 + wm * 64 + i * 16 + er;
        const int mg1 = mg0 + 8;
#pragma unroll
        for (int j = 0; j < 4; j++) {
            const int n = n0 + wn * 32 + j * 8 + ec;
            if (mg0 < Mcnt)
                *(float2*)&C[(size_t)mg0 * ldc + n] = make_float2(acc[i][j].x, acc[i][j].y);
            if (mg1 < Mcnt)
                *(float2*)&C[(size_t)mg1 * ldc + n] = make_float2(acc[i][j].z, acc[i][j].w);
        }
    }
}

// ---------------- GEMM wrappers ----------------
__global__ __launch_bounds__(256, 2)
void k_sh_gateup(const float* __restrict__ x, const float* __restrict__ Sg,
                 const float* __restrict__ Su) {
    const int mat = blockIdx.z;
    gemm_core(x, nullptr, DIM, mat ? Su : Sg, FSH,
              mat ? g_Us : g_Gs, FSH, T_TOK, DIM);
}

__global__ __launch_bounds__(256, 2)
void k_sh_down(const float* __restrict__ Sd, float* __restrict__ out) {
    gemm_core(g_Hs, nullptr, FSH, Sd, DIM, out, DIM, T_TOK, FSH);
}

__global__ __launch_bounds__(256, 2)
void k_moe_gateup(const float* __restrict__ x, const float* __restrict__ Wg,
                  const float* __restrict__ Wu) {
    const int z = blockIdx.z, e = z >> 1, mat = z & 1;
    const float* B = (mat ? Wu : Wg) + (size_t)e * DIM * FF;
    float*       C = (mat ? g_U : g_G) + (size_t)e * T_TOK * FF;
    gemm_core(x, g_tok[e], DIM, B, FF, C, FF, g_count[e], DIM);
}

__global__ __launch_bounds__(256, 2)
void k_moe_down(const float* __restrict__ Wd) {
    const int e = blockIdx.z;
    gemm_core(g_H + (size_t)e * T_TOK * FF, nullptr, FF,
              Wd + (size_t)e * FF * DIM, DIM,
              g_O + (size_t)e * T_TOK * DIM, DIM, g_count[e], FF);
}

// ---------------- elementwise silu*up (streaming, paid once) ----------------
__global__ void k_moe_silu() {
    const int e = blockIdx.y;
    const int total = g_count[e] * FF;
    const int idx = (blockIdx.x * 256 + threadIdx.x) * 4;
    if (idx >= total) return;
    const size_t base = (size_t)e * T_TOK * FF + idx;
    float4 g4 = *(const float4*)&g_G[base];
    float4 u4 = *(const float4*)&g_U[base];
    float4 h;
    h.x = silu_f(g4.x) * u4.x;
    h.y = silu_f(g4.y) * u4.y;
    h.z = silu_f(g4.z) * u4.z;
    h.w = silu_f(g4.w) * u4.w;
    *(float4*)&g_H[base] = h;
}

__global__ void k_sh_silu() {
    const size_t idx = ((size_t)blockIdx.x * 256 + threadIdx.x) * 4;
    float4 g4 = *(const float4*)&g_Gs[idx];
    float4 u4 = *(const float4*)&g_Us[idx];
    float4 h;
    h.x = silu_f(g4.x) * u4.x;
    h.y = silu_f(g4.y) * u4.y;
    h.z = silu_f(g4.z) * u4.z;
    h.w = silu_f(g4.w) * u4.w;
    *(float4*)&g_Hs[idx] = h;
}

// ---------------- final combine: out[t] += w0*O[s0] + w1*O[s1] ----------------
__global__ void k_combine(float* __restrict__ out) {
    const int t = blockIdx.x;
    const int i = threadIdx.x * 4;
    const int   s0 = g_eslot[0][t], s1 = g_eslot[1][t];
    const float w0 = g_ew[0][t],    w1 = g_ew[1][t];
    float4 o = *(float4*)&out[(size_t)t * DIM + i];
    float4 a = *(const float4*)&g_O[(size_t)s0 * DIM + i];
    float4 b = *(const float4*)&g_O[(size_t)s1 * DIM + i];
    o.x += w0 * a.x + w1 * b.x;
    o.y += w0 * a.y + w1 * b.y;
    o.z += w0 * a.z + w1 * b.z;
    o.w += w0 * a.w + w1 * b.w;
    *(float4*)&out[(size_t)t * DIM + i] = o;
}

// ---------------- launch ----------------
extern "C" void kernel_launch(void* const* d_in, const int* in_sizes, int n_in,
                              void* d_out, int out_size) {
    const float* x    = (const float*)d_in[0];
    const float* Wr   = (const float*)d_in[1];
    const float* Wg   = (const float*)d_in[2];
    const float* Wu   = (const float*)d_in[3];
    const float* Wd   = (const float*)d_in[4];
    const float* Sg   = (const float*)d_in[5];
    const float* Su   = (const float*)d_in[6];
    const float* Sd   = (const float*)d_in[7];
    const float* bias = (const float*)d_in[8];
    float* out = (float*)d_out;

    k_init<<<1, 32>>>();
    k_router<<<T_TOK / 8, dim3(32, 8)>>>(x, Wr, bias);

    // gate+up projections
    k_sh_gateup <<<dim3(FSH / 128, T_TOK / 128, 2),       256>>>(x, Sg, Su);
    k_moe_gateup<<<dim3(FF  / 128, T_TOK / 128, NEXP * 2), 256>>>(x, Wg, Wu);

    // elementwise SwiGLU (streaming, once)
    k_sh_silu <<<(T_TOK * FSH) / 1024, 256>>>();
    k_moe_silu<<<dim3((T_TOK * FF) / 1024, NEXP), 256>>>();

    // down projections
    k_sh_down <<<dim3(DIM / 128, T_TOK / 128),       256>>>(Sd, out);
    k_moe_down<<<dim3(DIM / 128, T_TOK / 128, NEXP), 256>>>(Wd);

    // combine routed outputs into shared-expert output
    k_combine<<<T_TOK, 256>>>(out);
}